// round 13
// baseline (speedup 1.0000x reference)
#include <cuda_runtime.h>
#include <cstdint>

// Embedding gather: out[r, :] = weight[ids[r], :]
// weight: [50257, 1024] fp32, ids: [32768] int32, out: [32768, 1024] fp32
//
// R13: union of proven-best halves.
//   - loads: plain C++ float4 gathers (R6 style) -> ptxas front-batches 8
//     independent LDG.128s, regs=32, occ~79% (highest-occupancy variant)
//   - stores: st.global.wt (R11's win: write-through, no L2 allocation churn
//     for the 128MB write-once output stream; best kernel time 34.8us)
// Cache-op experiments concluded: .cg / evict_last / .cs are all neutral or
// harmful; only .wt stores measurably help.

#define DIM4 256          // DIM/4 float4 per row
#define THREADS 256
#define ROWS_PER_CTA 8

__global__ __launch_bounds__(THREADS)
void embed_gather_kernel(const float4* __restrict__ weight,
                         const int* __restrict__ ids,
                         float4* __restrict__ out,
                         int n_rows)
{
    const int tid  = threadIdx.x;
    const int base = blockIdx.x * ROWS_PER_CTA;

    // 8 independent broadcast index loads (one scoreboard wait)
    int idx[ROWS_PER_CTA];
#pragma unroll
    for (int r = 0; r < ROWS_PER_CTA; r++)
        idx[r] = ids[base + r];

    // 8 independent 16B gathers — compiler-scheduled (front-batched)
    float4 v[ROWS_PER_CTA];
#pragma unroll
    for (int r = 0; r < ROWS_PER_CTA; r++)
        v[r] = weight[(size_t)idx[r] * DIM4 + tid];

    // 8 write-through stores (no L2 allocation for write-once output)
#pragma unroll
    for (int r = 0; r < ROWS_PER_CTA; r++) {
        float4* dst = out + (size_t)(base + r) * DIM4 + tid;
        asm volatile("st.global.wt.v4.f32 [%0], {%1, %2, %3, %4};"
                     :: "l"(dst),
                        "f"(v[r].x), "f"(v[r].y), "f"(v[r].z), "f"(v[r].w)
                     : "memory");
    }
}

extern "C" void kernel_launch(void* const* d_in, const int* in_sizes, int n_in,
                              void* d_out, int out_size)
{
    // Identify inputs by element count:
    //   weight: 50257*1024 = 51463168 elements; ids: 32768 elements
    const float4* weight;
    const int* ids;
    int n_rows;

    if (in_sizes[0] > in_sizes[1]) {
        weight = (const float4*)d_in[0];
        ids    = (const int*)d_in[1];
        n_rows = in_sizes[1];
    } else {
        weight = (const float4*)d_in[1];
        ids    = (const int*)d_in[0];
        n_rows = in_sizes[0];
    }

    int n_blocks = n_rows / ROWS_PER_CTA;  // 32768/8 = 4096, exact
    embed_gather_kernel<<<n_blocks, THREADS>>>(weight, ids, (float4*)d_out, n_rows);
}